// round 5
// baseline (speedup 1.0000x reference)
#include <cuda_runtime.h>
#include <cuda_bf16.h>
#include <cstdint>

// Problem constants
#define B_   8
#define TGT  256
#define SRC  256
#define DM   512
#define LDIM 256
#define LOGEPS (-18.420680743952367f)   // log(1e-8)

// -------- scratch (device globals; no allocation) --------
__device__ float g_dt[B_ * TGT * LDIM];   // dec @ W1
__device__ float g_et[B_ * SRC * LDIM];   // enc @ W2

// ---------------- helpers ----------------
__device__ __forceinline__ float tanhapx(float x) {
    float y;
    asm("tanh.approx.f32 %0, %1;" : "=f"(y) : "f"(x));
    return y;
}
__device__ __forceinline__ unsigned long long pk2(float x) {
    unsigned long long r;
    asm("mov.b64 %0, {%1, %1};" : "=l"(r) : "f"(x));
    return r;
}
__device__ __forceinline__ unsigned long long fma2(unsigned long long a,
                                                   unsigned long long b,
                                                   unsigned long long c) {
    unsigned long long d;
    asm("fma.rn.f32x2 %0, %1, %2, %3;" : "=l"(d) : "l"(a), "l"(b), "l"(c));
    return d;
}
__device__ __forceinline__ void unpk2(unsigned long long v, float& lo, float& hi) {
    asm("mov.b64 {%0, %1}, %2;" : "=f"(lo), "=f"(hi) : "l"(v));
}
__device__ __forceinline__ void cp_async16(void* smem_dst, const void* gmem_src) {
    unsigned saddr = (unsigned)__cvta_generic_to_shared(smem_dst);
    asm volatile("cp.async.ca.shared.global [%0], [%1], 16;"
                 :: "r"(saddr), "l"(gmem_src));
}
__device__ __forceinline__ void cp_commit() {
    asm volatile("cp.async.commit_group;" ::: "memory");
}
__device__ __forceinline__ void cp_wait0() {
    asm volatile("cp.async.wait_group 0;" ::: "memory");
}

// =====================================================================
// Kernel A: Y = X @ W.  X:[2048,512] W:[512,256] Y:[2048,256]
// 64x64 tile, BK=16, 256 threads, 4x4/thread, f32x2 FFMA,
// cp.async double-buffered stages (1 barrier per k-tile).
// =====================================================================
#define AK 20     // padded k-stride for As[m][k]
#define BN 68     // padded n-stride for Bs[k][n]

__global__ __launch_bounds__(256) void gemm64_kernel(
    const float* __restrict__ dec, const float* __restrict__ enc,
    const float* __restrict__ W1,  const float* __restrict__ W2)
{
    const float* X; const float* W; float* Y;
    if (blockIdx.z == 0) { X = dec; W = W1; Y = g_dt; }
    else                 { X = enc; W = W2; Y = g_et; }

    __shared__ float As[2][64 * AK];   // [m][k] natural layout
    __shared__ float Bs[2][16 * BN];   // [k][n] natural layout

    const int tid = threadIdx.x;
    const int tx  = tid & 15;          // n (x4)
    const int ty  = tid >> 4;          // m (x4)
    const int m0  = blockIdx.y * 64;
    const int n0  = blockIdx.x * 64;

    // stage-load assignments (one cp.async16 each for A and B)
    const int am = tid >> 2;           // 0..63
    const int ak = (tid & 3) * 4;      // 0,4,8,12
    const int bk = tid >> 4;           // 0..15
    const int bn = (tid & 15) * 4;     // 0..60

    const float* Ag = X + (size_t)(m0 + am) * DM + ak;
    const float* Bg = W + (size_t)bk * LDIM + n0 + bn;

    // prefetch stage 0
    cp_async16(&As[0][am * AK + ak], Ag);
    cp_async16(&Bs[0][bk * BN + bn], Bg);
    cp_commit();

    unsigned long long acc[4][2];
#pragma unroll
    for (int i = 0; i < 4; i++) { acc[i][0] = 0ull; acc[i][1] = 0ull; }

#pragma unroll 1
    for (int kt = 0; kt < DM / 16; kt++) {
        cp_wait0();
        __syncthreads();               // stage kt ready; prior reads done

        if (kt + 1 < DM / 16) {
            int nb = (kt + 1) & 1;
            cp_async16(&As[nb][am * AK + ak], Ag + (kt + 1) * 16);
            cp_async16(&Bs[nb][bk * BN + bn], Bg + (size_t)(kt + 1) * 16 * LDIM);
            cp_commit();
        }

        const float* Ab = &As[kt & 1][ty * 4 * AK];
        const float* Bb = &Bs[kt & 1][tx * 4];
#pragma unroll
        for (int k = 0; k < 16; k++) {
            ulonglong2 bb = *(const ulonglong2*)&Bb[k * BN];
            float a0 = Ab[0 * AK + k];
            float a1 = Ab[1 * AK + k];
            float a2 = Ab[2 * AK + k];
            float a3 = Ab[3 * AK + k];
            unsigned long long p0 = pk2(a0), p1 = pk2(a1),
                               p2 = pk2(a2), p3 = pk2(a3);
            acc[0][0] = fma2(p0, bb.x, acc[0][0]);
            acc[0][1] = fma2(p0, bb.y, acc[0][1]);
            acc[1][0] = fma2(p1, bb.x, acc[1][0]);
            acc[1][1] = fma2(p1, bb.y, acc[1][1]);
            acc[2][0] = fma2(p2, bb.x, acc[2][0]);
            acc[2][1] = fma2(p2, bb.y, acc[2][1]);
            acc[3][0] = fma2(p3, bb.x, acc[3][0]);
            acc[3][1] = fma2(p3, bb.y, acc[3][1]);
        }
        __syncthreads();               // reads of stage kt done before overwrite
    }

#pragma unroll
    for (int i = 0; i < 4; i++) {
        float4 o;
        unpk2(acc[i][0], o.x, o.y);
        unpk2(acc[i][1], o.z, o.w);
        *(float4*)&Y[(size_t)(m0 + ty * 4 + i) * LDIM + n0 + tx * 4] = o;
    }
}

// =====================================================================
// Kernel B: fused scores + mask + log_softmax + transposed write.
// Grid (TGT/8, B) = (32, 8) = 256 blocks, 256 threads, occ 2.
// Block owns t-rows t0..t0+7 of batch b; warp w owns row t0+w.
// s processed in 8 tiles of 32 (double-buffered cp.async); lane = s-in-tile.
// smem (floats):
//   sDt [8][260]     @ 0      (2080)
//   sEt [2][32][260] @ 2080   (16640)
//   sSc [8][257]     @ 18720  (2056)
//   sVt [256]        @ 20776
//   sLse[8]          @ 21032
// total 21040 floats = 84160 B  ->  2 blocks/SM (168 KB)
// =====================================================================
#define LPAD 260
#define SPAD 257
#define OFF_ET  2080
#define OFF_SC  18720
#define OFF_VT  20776
#define OFF_LSE 21032
#define SMEM_B_BYTES (21040 * 4)

__device__ __forceinline__ void load_et32(float* dst, const float* src, int tid) {
#pragma unroll
    for (int i = 0; i < 8; i++) {
        int idx = tid + i * 256;        // float4 idx 0..2047 (32 rows x 64)
        int r = idx >> 6, c = idx & 63;
        cp_async16(&dst[r * LPAD + c * 4], src + r * LDIM + c * 4);
    }
    cp_commit();
}

__global__ __launch_bounds__(256, 2) void attn_kernel(
    const int* __restrict__ lens, const float* __restrict__ vt,
    float* __restrict__ out)
{
    extern __shared__ float sm[];
    float* sDt  = sm;
    float* sEt  = sm + OFF_ET;
    float* sSc  = sm + OFF_SC;
    float* sVt  = sm + OFF_VT;
    float* sLse = sm + OFF_LSE;

    const int tid = threadIdx.x;
    const int b   = blockIdx.y;
    const int t0  = blockIdx.x * 8;

    const float* dtB = g_dt + ((size_t)b * TGT + t0) * LDIM;   // [8][256]
    const float* etB = g_et + (size_t)b * SRC * LDIM;          // [256][256]

    // prefetch et tile 0 (async); dt + vt on sync path
    load_et32(sEt, etB, tid);
#pragma unroll
    for (int i = 0; i < 2; i++) {
        int idx = tid + i * 256;        // float4 idx 0..511 (8 rows x 64)
        int r = idx >> 6, c = idx & 63;
        float4 v = ((const float4*)dtB)[idx];
        *(float4*)&sDt[r * LPAD + c * 4] = v;
    }
    if (tid < 64) ((float4*)sVt)[tid] = ((const float4*)vt)[tid];

    cp_wait0();
    __syncthreads();

    const int w    = tid >> 5;
    const int lane = tid & 31;
    const float* dR = &sDt[w * LPAD];

#pragma unroll 1
    for (int st = 0; st < 8; st++) {
        const float* cur = sEt + (st & 1) * (32 * LPAD);
        if (st < 7)
            load_et32(sEt + ((st + 1) & 1) * (32 * LPAD),
                      etB + (st + 1) * 32 * LDIM, tid);

        const float* eR = &cur[lane * LPAD];
        float acc = 0.f;
#pragma unroll 4
        for (int l = 0; l < 256; l += 4) {
            float4 vv = *(const float4*)&sVt[l];
            float4 d  = *(const float4*)&dR[l];
            float4 e  = *(const float4*)&eR[l];
            acc += tanhapx(d.x + e.x) * vv.x;
            acc += tanhapx(d.y + e.y) * vv.y;
            acc += tanhapx(d.z + e.z) * vv.z;
            acc += tanhapx(d.w + e.w) * vv.w;
        }
        sSc[w * SPAD + st * 32 + lane] = acc;

        if (st < 7) cp_wait0();
        __syncthreads();
    }

    // ---- masked log_softmax over s: warp w handles row w ----
    const int len = lens[b];
    {
        float v[8];
        float mx = -3.0e38f;
#pragma unroll
        for (int i = 0; i < 8; i++) {
            int s = lane + 32 * i;
            float x = sSc[w * SPAD + s];
            if (s >= len) x += LOGEPS;
            v[i] = x;
            mx = fmaxf(mx, x);
        }
#pragma unroll
        for (int o = 16; o > 0; o >>= 1)
            mx = fmaxf(mx, __shfl_xor_sync(0xffffffffu, mx, o));
        float sum = 0.f;
#pragma unroll
        for (int i = 0; i < 8; i++) sum += __expf(v[i] - mx);
#pragma unroll
        for (int o = 16; o > 0; o >>= 1)
            sum += __shfl_xor_sync(0xffffffffu, sum, o);
        if (lane == 0) sLse[w] = mx + __logf(sum);
    }
    __syncthreads();

    // ---- transposed write: out[b][s][t0+lt] ----
    float* outB = out + (size_t)b * SRC * TGT + t0;
    const int lt = tid & 7;
    const int sB = tid >> 3;            // 0..31
    const float lse = sLse[lt];
#pragma unroll
    for (int p = 0; p < 8; p++) {
        int s = sB + p * 32;
        float x = sSc[lt * SPAD + s];
        if (s >= len) x += LOGEPS;
        outB[(size_t)s * TGT + lt] = x - lse;
    }
}

// =====================================================================
// launcher
// =====================================================================
extern "C" void kernel_launch(void* const* d_in, const int* in_sizes, int n_in,
                              void* d_out, int out_size)
{
    const float* dec = (const float*)d_in[0];   // [8,256,512]
    const float* enc = (const float*)d_in[1];   // [8,256,512]
    const int*   len = (const int*)  d_in[2];   // [8]
    const float* W1  = (const float*)d_in[3];   // [512,256]
    const float* W2  = (const float*)d_in[4];   // [512,256]
    const float* vt  = (const float*)d_in[5];   // [256]
    float* out = (float*)d_out;                 // [8,256,256] = [b][s][t]

    (void)in_sizes; (void)n_in; (void)out_size;

    cudaFuncSetAttribute(attn_kernel,
                         cudaFuncAttributeMaxDynamicSharedMemorySize,
                         SMEM_B_BYTES);

    dim3 gGemm(LDIM / 64, (B_ * TGT) / 64, 2);   // (4, 32, 2)
    gemm64_kernel<<<gGemm, 256>>>(dec, enc, W1, W2);

    dim3 gAttn(TGT / 8, B_);                     // (32, 8)
    attn_kernel<<<gAttn, 256, SMEM_B_BYTES>>>(len, vt, out);
}

// round 6
// speedup vs baseline: 1.7388x; 1.7388x over previous
#include <cuda_runtime.h>
#include <cuda_bf16.h>
#include <cstdint>

// Problem constants
#define B_   8
#define TGT  256
#define SRC  256
#define DM   512
#define LDIM 256
#define LOGEPS (-18.420680743952367f)   // log(1e-8)

// -------- scratch (device globals; no allocation) --------
__device__ float g_dt[B_ * TGT * LDIM];   // dec @ W1
__device__ float g_et[B_ * SRC * LDIM];   // enc @ W2

// ---------------- helpers ----------------
__device__ __forceinline__ float tanhapx(float x) {
    float y;
    asm("tanh.approx.f32 %0, %1;" : "=f"(y) : "f"(x));
    return y;
}
__device__ __forceinline__ unsigned long long pk2(float x) {
    unsigned long long r;
    asm("mov.b64 %0, {%1, %1};" : "=l"(r) : "f"(x));
    return r;
}
__device__ __forceinline__ unsigned long long fma2(unsigned long long a,
                                                   unsigned long long b,
                                                   unsigned long long c) {
    unsigned long long d;
    asm("fma.rn.f32x2 %0, %1, %2, %3;" : "=l"(d) : "l"(a), "l"(b), "l"(c));
    return d;
}
__device__ __forceinline__ void unpk2(unsigned long long v, float& lo, float& hi) {
    asm("mov.b64 {%0, %1}, %2;" : "=f"(lo), "=f"(hi) : "l"(v));
}
__device__ __forceinline__ void cp_async16(void* smem_dst, const void* gmem_src) {
    unsigned saddr = (unsigned)__cvta_generic_to_shared(smem_dst);
    asm volatile("cp.async.ca.shared.global [%0], [%1], 16;"
                 :: "r"(saddr), "l"(gmem_src));
}
__device__ __forceinline__ void cp_commit() {
    asm volatile("cp.async.commit_group;" ::: "memory");
}
__device__ __forceinline__ void cp_wait0() {
    asm volatile("cp.async.wait_group 0;" ::: "memory");
}

// =====================================================================
// Kernel A: Y = X @ W.  X:[2048,512] W:[512,256] Y:[2048,256]
// 128x64 tile, BK=16, 256 threads, 8m x 4n per thread, f32x2 FFMA.
// Grid (4 n-tiles, 16 m-tiles, 2 inputs) = 128 blocks -> exactly 1 wave.
// =====================================================================
#define APAD 132   // As row stride (128 m + pad)
#define BPAD 68    // Bs row stride (64 n + pad)

__global__ __launch_bounds__(256) void gemm128_kernel(
    const float* __restrict__ dec, const float* __restrict__ enc,
    const float* __restrict__ W1,  const float* __restrict__ W2)
{
    const float* X; const float* W; float* Y;
    if (blockIdx.z == 0) { X = dec; W = W1; Y = g_dt; }
    else                 { X = enc; W = W2; Y = g_et; }

    __shared__ float As[16 * APAD];   // [k][m]
    __shared__ float Bs[16 * BPAD];   // [k][n]

    const int tid = threadIdx.x;
    const int tx  = tid & 15;          // n (x4)
    const int ty  = tid >> 4;          // m (x8)
    const int m0  = blockIdx.y * 128;
    const int n0  = blockIdx.x * 64;

    // global load assignments
    // A: 128 rows x 16 k = 512 float4; 2 per thread
    //   idx = tid + 256*i : am = idx>>2 (0..127), ak = (idx&3)*4
    // B: 16 k x 64 n = 256 float4; 1 per thread
    //   bk = tid>>4 (0..15), bn = (tid&15)*4
    const int am0 = tid >> 2;
    const int ak  = (tid & 3) * 4;
    const int bk  = tid >> 4;
    const int bn  = (tid & 15) * 4;

    const float* Ag0 = X + (size_t)(m0 + am0)       * DM + ak;
    const float* Ag1 = X + (size_t)(m0 + am0 + 64)  * DM + ak;
    const float* Bg  = W + (size_t)bk * LDIM + n0 + bn;

    unsigned long long acc[8][2];
#pragma unroll
    for (int i = 0; i < 8; i++) { acc[i][0] = 0ull; acc[i][1] = 0ull; }

#pragma unroll 1
    for (int kt = 0; kt < DM / 16; kt++) {
        float4 a0 = *(const float4*)(Ag0 + kt * 16);
        float4 a1 = *(const float4*)(Ag1 + kt * 16);
        float4 b  = *(const float4*)(Bg + (size_t)kt * 16 * LDIM);
        __syncthreads();
        As[(ak + 0) * APAD + am0]      = a0.x;
        As[(ak + 1) * APAD + am0]      = a0.y;
        As[(ak + 2) * APAD + am0]      = a0.z;
        As[(ak + 3) * APAD + am0]      = a0.w;
        As[(ak + 0) * APAD + am0 + 64] = a1.x;
        As[(ak + 1) * APAD + am0 + 64] = a1.y;
        As[(ak + 2) * APAD + am0 + 64] = a1.z;
        As[(ak + 3) * APAD + am0 + 64] = a1.w;
        *(float4*)&Bs[bk * BPAD + bn]  = b;
        __syncthreads();

#pragma unroll
        for (int k = 0; k < 16; k++) {
            float4 av0 = *(const float4*)&As[k * APAD + ty * 8];
            float4 av1 = *(const float4*)&As[k * APAD + ty * 8 + 4];
            ulonglong2 bb = *(const ulonglong2*)&Bs[k * BPAD + tx * 4];
            float am[8] = {av0.x, av0.y, av0.z, av0.w,
                           av1.x, av1.y, av1.z, av1.w};
#pragma unroll
            for (int i = 0; i < 8; i++) {
                unsigned long long p = pk2(am[i]);
                acc[i][0] = fma2(p, bb.x, acc[i][0]);
                acc[i][1] = fma2(p, bb.y, acc[i][1]);
            }
        }
    }

#pragma unroll
    for (int i = 0; i < 8; i++) {
        float4 o;
        unpk2(acc[i][0], o.x, o.y);
        unpk2(acc[i][1], o.z, o.w);
        *(float4*)&Y[(size_t)(m0 + ty * 8 + i) * LDIM + n0 + tx * 4] = o;
    }
}

// =====================================================================
// Kernel B: fused scores + mask + log_softmax + transposed write.
// Grid (16, 8) = 128 blocks, 512 threads (16 warps/SM, 4/SMSP).
// Block owns t-rows t0..t0+15 of batch b.
// Warp w: t-pair p = w>>1 (rows 2p, 2p+1), s-half h = w&1.
// s tiled in 4 tiles of 64 (double-buffered cp.async);
// warp covers s = st*64 + h*32 + lane.
// smem (floats):
//   sDt [16][260]     @ 0      (4160)
//   sEt [2][64][260]  @ 4160   (33280)
//   sSc [16][257]     @ 37440  (4112)
//   sVt [256]         @ 41552
//   sLse[16]          @ 41808
// total 41824 floats = 167296 B
// =====================================================================
#define LPAD 260
#define SPAD 257
#define OFF_ET  4160
#define OFF_SC  37440
#define OFF_VT  41552
#define OFF_LSE 41808
#define SMEM_B_BYTES (41824 * 4)

__device__ __forceinline__ void load_et64(float* dst, const float* src, int tid) {
#pragma unroll
    for (int i = 0; i < 8; i++) {
        int idx = tid + i * 512;        // float4 idx 0..4095 (64 rows x 64)
        int r = idx >> 6, c = idx & 63;
        cp_async16(&dst[r * LPAD + c * 4], src + r * LDIM + c * 4);
    }
    cp_commit();
}

__global__ __launch_bounds__(512, 1) void attn_kernel(
    const int* __restrict__ lens, const float* __restrict__ vt,
    float* __restrict__ out)
{
    extern __shared__ float sm[];
    float* sDt  = sm;
    float* sEt  = sm + OFF_ET;
    float* sSc  = sm + OFF_SC;
    float* sVt  = sm + OFF_VT;
    float* sLse = sm + OFF_LSE;

    const int tid = threadIdx.x;
    const int b   = blockIdx.y;
    const int t0  = blockIdx.x * 16;

    const float* dtB = g_dt + ((size_t)b * TGT + t0) * LDIM;   // [16][256]
    const float* etB = g_et + (size_t)b * SRC * LDIM;          // [256][256]

    // prefetch et tile 0 (async); dt + vt on sync path
    load_et64(sEt, etB, tid);
#pragma unroll
    for (int i = 0; i < 2; i++) {
        int idx = tid + i * 512;        // float4 idx 0..1023 (16 rows x 64)
        int r = idx >> 6, c = idx & 63;
        float4 v = ((const float4*)dtB)[idx];
        *(float4*)&sDt[r * LPAD + c * 4] = v;
    }
    if (tid < 64) ((float4*)sVt)[tid] = ((const float4*)vt)[tid];

    cp_wait0();
    __syncthreads();

    const int w    = tid >> 5;
    const int lane = tid & 31;
    const int p    = w >> 1;            // t-pair 0..7
    const int h    = w & 1;             // s-half 0/1
    const float* dR0 = &sDt[(2 * p) * LPAD];
    const float* dR1 = &sDt[(2 * p + 1) * LPAD];

#pragma unroll 1
    for (int st = 0; st < 4; st++) {
        const float* cur = sEt + (st & 1) * (64 * LPAD);
        if (st < 3)
            load_et64(sEt + ((st + 1) & 1) * (64 * LPAD),
                      etB + (st + 1) * 64 * LDIM, tid);

        const float* eR = &cur[(h * 32 + lane) * LPAD];
        float a0 = 0.f, a1 = 0.f;
#pragma unroll 8
        for (int l = 0; l < 256; l += 4) {
            float4 vv = *(const float4*)&sVt[l];
            float4 d0 = *(const float4*)&dR0[l];
            float4 d1 = *(const float4*)&dR1[l];
            float4 e  = *(const float4*)&eR[l];
            a0 += tanhapx(d0.x + e.x) * vv.x;
            a1 += tanhapx(d1.x + e.x) * vv.x;
            a0 += tanhapx(d0.y + e.y) * vv.y;
            a1 += tanhapx(d1.y + e.y) * vv.y;
            a0 += tanhapx(d0.z + e.z) * vv.z;
            a1 += tanhapx(d1.z + e.z) * vv.z;
            a0 += tanhapx(d0.w + e.w) * vv.w;
            a1 += tanhapx(d1.w + e.w) * vv.w;
        }

        const int sg = st * 64 + h * 32 + lane;
        sSc[(2 * p) * SPAD + sg]     = a0;
        sSc[(2 * p + 1) * SPAD + sg] = a1;

        if (st < 3) cp_wait0();
        __syncthreads();
    }

    // ---- masked log_softmax over s: warp w handles row w (w<16) ----
    const int len = lens[b];
    if (w < 16) {
        float v[8];
        float mx = -3.0e38f;
#pragma unroll
        for (int i = 0; i < 8; i++) {
            int s = lane + 32 * i;
            float x = sSc[w * SPAD + s];
            if (s >= len) x += LOGEPS;
            v[i] = x;
            mx = fmaxf(mx, x);
        }
#pragma unroll
        for (int o = 16; o > 0; o >>= 1)
            mx = fmaxf(mx, __shfl_xor_sync(0xffffffffu, mx, o));
        float sum = 0.f;
#pragma unroll
        for (int i = 0; i < 8; i++) sum += __expf(v[i] - mx);
#pragma unroll
        for (int o = 16; o > 0; o >>= 1)
            sum += __shfl_xor_sync(0xffffffffu, sum, o);
        if (lane == 0) sLse[w] = mx + __logf(sum);
    }
    __syncthreads();

    // ---- transposed write: out[b][s][t0+lt] ----
    float* outB = out + (size_t)b * SRC * TGT + t0;
    const int lt = tid & 15;
    const int sB = tid >> 4;            // 0..31
    const float lse = sLse[lt];
#pragma unroll
    for (int pp = 0; pp < 8; pp++) {
        int s = sB + pp * 32;
        float x = sSc[lt * SPAD + s];
        if (s >= len) x += LOGEPS;
        outB[(size_t)s * TGT + lt] = x - lse;
    }
}

// =====================================================================
// launcher
// =====================================================================
extern "C" void kernel_launch(void* const* d_in, const int* in_sizes, int n_in,
                              void* d_out, int out_size)
{
    const float* dec = (const float*)d_in[0];   // [8,256,512]
    const float* enc = (const float*)d_in[1];   // [8,256,512]
    const int*   len = (const int*)  d_in[2];   // [8]
    const float* W1  = (const float*)d_in[3];   // [512,256]
    const float* W2  = (const float*)d_in[4];   // [512,256]
    const float* vt  = (const float*)d_in[5];   // [256]
    float* out = (float*)d_out;                 // [8,256,256] = [b][s][t]

    (void)in_sizes; (void)n_in; (void)out_size;

    cudaFuncSetAttribute(attn_kernel,
                         cudaFuncAttributeMaxDynamicSharedMemorySize,
                         SMEM_B_BYTES);

    dim3 gGemm(LDIM / 64, (B_ * TGT) / 128, 2);  // (4, 16, 2) = 128 blocks
    gemm128_kernel<<<gGemm, 256>>>(dec, enc, W1, W2);

    dim3 gAttn(TGT / 16, B_);                    // (16, 8) = 128 blocks
    attn_kernel<<<gAttn, 512, SMEM_B_BYTES>>>(len, vt, out);
}